// round 2
// baseline (speedup 1.0000x reference)
#include <cuda_runtime.h>
#include <math.h>

#define A_NUM   9
#define C_NUM   20
#define OUTCH   65          // 5*A_NUM + C_NUM
#define BATCH   32
#define KDIM    256         // Cin == hidden == 256
#define HH      56
#define WW      56
#define HW      3136        // 56*56
#define NBOX    64
#define MPOS    2048

// Scratch (no cudaMalloc allowed): hidden activations + stage-2 conv output
__device__ float g_hidden[BATCH * KDIM * HW];    // 32*256*3136 fp32 = ~103 MB
__device__ float g_out2  [BATCH * OUTCH * HW];   // 32*65*3136  fp32 = ~26 MB

// ---------------------------------------------------------------------------
// 1x1 conv as tiled GEMM:  Y[b][m][p] = act( sum_c W[m][c] * X[b][c][p] + bias[m] )
// BM=128, BN=128, BK=16, 256 threads, 8x8 register tile per thread.
// ---------------------------------------------------------------------------
template<int MROWS, bool LEAKY, bool FIRST>
__global__ __launch_bounds__(256)
void conv_gemm(const float* __restrict__ Xin,
               const float* __restrict__ Wm,
               const float* __restrict__ bias)
{
    const int b     = blockIdx.z;
    const int mBase = blockIdx.y * 128;
    const int nBase = blockIdx.x * 128;

    const float* Xb = (FIRST ? Xin : (const float*)g_hidden) + (size_t)b * KDIM * HW;
    float*       Yb = (FIRST ? g_hidden : g_out2) + (size_t)b * MROWS * HW;

    __shared__ float As[16][128];   // A tile transposed: As[k][m]
    __shared__ float Bs[16][128];   // Bs[k][p]

    const int tid = threadIdx.x;
    const int tr  = tid >> 4;       // 0..15 (m direction)
    const int tc  = tid & 15;       // 0..15 (p direction)

    float acc[8][8];
    #pragma unroll
    for (int i = 0; i < 8; i++)
        #pragma unroll
        for (int j = 0; j < 8; j++) acc[i][j] = 0.f;

    for (int k0 = 0; k0 < KDIM; k0 += 16) {
        // Load A tile: rows mBase..+127, cols k0..+15  (512 float4, 2 per thread)
        #pragma unroll
        for (int i = 0; i < 2; i++) {
            int idx  = tid + i * 256;
            int row  = idx >> 2;            // 0..127
            int c4   = (idx & 3) * 4;       // 0,4,8,12
            int gm   = mBase + row;
            float4 v = make_float4(0.f, 0.f, 0.f, 0.f);
            if (gm < MROWS)
                v = *(const float4*)(Wm + (size_t)gm * KDIM + k0 + c4);
            As[c4 + 0][row] = v.x;
            As[c4 + 1][row] = v.y;
            As[c4 + 2][row] = v.z;
            As[c4 + 3][row] = v.w;
        }
        // Load B tile: channels k0..+15, pixels nBase..+127
        #pragma unroll
        for (int i = 0; i < 2; i++) {
            int idx = tid + i * 256;
            int row = idx >> 5;             // 0..15
            int c4  = (idx & 31) * 4;       // 0..124
            int p   = nBase + c4;
            float4 v = make_float4(0.f, 0.f, 0.f, 0.f);
            if (p < HW)   // HW%4==0 and p%4==0 -> full float4 in-bounds
                v = *(const float4*)(Xb + (size_t)(k0 + row) * HW + p);
            *(float4*)&Bs[row][c4] = v;
        }
        __syncthreads();

        #pragma unroll
        for (int k = 0; k < 16; k++) {
            float a[8], bb[8];
            *(float4*)&a[0]  = *(const float4*)&As[k][tr * 8];
            *(float4*)&a[4]  = *(const float4*)&As[k][tr * 8 + 4];
            *(float4*)&bb[0] = *(const float4*)&Bs[k][tc * 8];
            *(float4*)&bb[4] = *(const float4*)&Bs[k][tc * 8 + 4];
            #pragma unroll
            for (int i = 0; i < 8; i++)
                #pragma unroll
                for (int j = 0; j < 8; j++)
                    acc[i][j] = fmaf(a[i], bb[j], acc[i][j]);
        }
        __syncthreads();
    }

    // Epilogue: bias (+ leaky relu), masked store
    #pragma unroll
    for (int i = 0; i < 8; i++) {
        int m = mBase + tr * 8 + i;
        if (m < MROWS) {
            float bv = bias[m];
            #pragma unroll
            for (int j = 0; j < 8; j += 4) {
                int p = nBase + tc * 8 + j;
                if (p < HW) {
                    float4 v;
                    v.x = acc[i][j + 0] + bv;
                    v.y = acc[i][j + 1] + bv;
                    v.z = acc[i][j + 2] + bv;
                    v.w = acc[i][j + 3] + bv;
                    if (LEAKY) {
                        v.x = v.x >= 0.f ? v.x : 0.01f * v.x;
                        v.y = v.y >= 0.f ? v.y : 0.01f * v.y;
                        v.z = v.z >= 0.f ? v.z : 0.01f * v.z;
                        v.w = v.w >= 0.f ? v.w : 0.01f * v.w;
                    }
                    *(float4*)&Yb[(size_t)m * HW + p] = v;
                }
            }
        }
    }
}

// ---------------------------------------------------------------------------
// Head: proposals + IoU matrix. One thread per (b, a, pixel); writes 64 IoUs.
// grid = (25, A_NUM, BATCH), block = 128
// NOTE: iou_out is offset by 1 float from the harness buffer base -> NOT
// 16B-aligned. Scalar stores only (STG.128 on 4B-aligned addr traps).
// ---------------------------------------------------------------------------
__global__ __launch_bounds__(128)
void head_kernel(const float* __restrict__ anc,
                 const float* __restrict__ bboxes,
                 float* __restrict__ iou_out)
{
    __shared__ float bx1[NBOX], by1[NBOX], bx2[NBOX], by2[NBOX], ga[NBOX];
    const int b = blockIdx.z;
    const int a = blockIdx.y;
    const int tid = threadIdx.x;

    if (tid < NBOX) {
        const float* bb = bboxes + ((size_t)b * NBOX + tid) * 5;
        float x1 = bb[0], y1 = bb[1], x2 = bb[2], y2 = bb[3];
        bx1[tid] = x1; by1[tid] = y1; bx2[tid] = x2; by2[tid] = y2;
        ga[tid] = (x2 - x1) * (y2 - y1);
    }
    __syncthreads();

    const int p = blockIdx.x * 128 + tid;
    if (p >= HW) return;
    const int h = p / WW;
    const int w = p % WW;

    const float* o = g_out2 + (size_t)b * OUTCH * HW;
    float tx = o[(5 * a + 1) * HW + p];
    float ty = o[(5 * a + 2) * HW + p];
    float tw = o[(5 * a + 3) * HW + p];
    float th = o[(5 * a + 4) * HW + p];

    float wa = anc[a * 2 + 0], ha = anc[a * 2 + 1];
    float cx = (w + 0.5f) + tx;
    float cy = (h + 0.5f) + ty;
    float nw = wa * expf(tw);
    float nh = ha * expf(th);
    float px1 = cx - nw * 0.5f, px2 = cx + nw * 0.5f;
    float py1 = cy - nh * 0.5f, py2 = cy + nh * 0.5f;
    float parea = (px2 - px1) * (py2 - py1);

    float* orow = iou_out + (((size_t)b * (A_NUM * HW)) + (size_t)a * HW + p) * NBOX;
    #pragma unroll 4
    for (int g = 0; g < NBOX; g++) {
        float ix1 = fmaxf(px1, bx1[g]);
        float iy1 = fmaxf(py1, by1[g]);
        float ix2 = fminf(px2, bx2[g]);
        float iy2 = fminf(py2, by2[g]);
        float inter = fmaxf(ix2 - ix1, 0.f) * fmaxf(iy2 - iy1, 0.f);
        orow[g] = inter / (ga[g] + parea - inter);
    }
}

// ---------------------------------------------------------------------------
// Loss: single block deterministic reduction over 2048 pos + 2048 neg anchors
// ---------------------------------------------------------------------------
__global__ __launch_bounds__(256)
void loss_kernel(const int* __restrict__ pos_idx,
                 const int* __restrict__ neg_idx,
                 const float* __restrict__ gt_off,
                 float* __restrict__ out0)
{
    __shared__ float red[256];
    const int tid = threadIdx.x;
    float s = 0.f;

    for (int m = tid; m < MPOS; m += 256) {
        // positive anchor: conf loss (target 1) + regression loss
        int idx = pos_idx[m];
        int b   = idx / (A_NUM * HW);
        int rem = idx % (A_NUM * HW);
        int a   = rem / HW;
        int p   = rem % HW;
        const float* o = g_out2 + ((size_t)b * OUTCH + 5 * a) * HW + p;
        float c  = o[0];
        float sc = 1.f / (1.f + expf(-c));
        float d  = sc - 1.f;
        s += 0.5f * d * d;                 // conf term, /(2M) applied via /M later
        #pragma unroll
        for (int k = 0; k < 4; k++) {
            float dd = o[(size_t)(1 + k) * HW] - gt_off[m * 4 + k];
            s += dd * dd;                  // reg term, /M later
        }
        // negative anchor: conf loss (target 0)
        int nidx = neg_idx[m];
        int nb   = nidx / (A_NUM * HW);
        int nrem = nidx % (A_NUM * HW);
        int na   = nrem / HW;
        int np   = nrem % HW;
        float nc = g_out2[((size_t)nb * OUTCH + 5 * na) * HW + np];
        float nsc = 1.f / (1.f + expf(-nc));
        s += 0.5f * nsc * nsc;
    }

    red[tid] = s;
    __syncthreads();
    for (int st = 128; st > 0; st >>= 1) {
        if (tid < st) red[tid] += red[tid + st];
        __syncthreads();
    }
    if (tid == 0) out0[0] = red[0] / (float)MPOS;
}

// ---------------------------------------------------------------------------
// class_pos gather: out[m][c] = out2[b, 5A + c, hw]  for positive anchors
// ---------------------------------------------------------------------------
__global__ __launch_bounds__(256)
void class_kernel(const int* __restrict__ pos_idx,
                  float* __restrict__ out_cls)
{
    int t = blockIdx.x * blockDim.x + threadIdx.x;
    if (t >= MPOS * C_NUM) return;
    int m = t / C_NUM;
    int c = t % C_NUM;
    int idx = pos_idx[m];
    int b = idx / (A_NUM * HW);
    int p = idx % HW;
    out_cls[t] = g_out2[((size_t)b * OUTCH + 5 * A_NUM + c) * HW + p];
}

// ---------------------------------------------------------------------------
extern "C" void kernel_launch(void* const* d_in, const int* in_sizes, int n_in,
                              void* d_out, int out_size)
{
    const float* features = (const float*)d_in[0];
    const float* w1       = (const float*)d_in[1];
    const float* b1       = (const float*)d_in[2];
    const float* w2       = (const float*)d_in[3];
    const float* b2       = (const float*)d_in[4];
    const float* anc      = (const float*)d_in[5];
    // d_in[6] = grid (recomputed analytically: gx=w+0.5, gy=h+0.5)
    const float* bboxes   = (const float*)d_in[7];
    const float* gt_off   = (const float*)d_in[8];
    const int*   pos_idx  = (const int*)d_in[9];
    const int*   neg_idx  = (const int*)d_in[10];

    float* out      = (float*)d_out;
    float* loss_out = out;                                   // [1]
    float* iou_out  = out + 1;                               // [B, A*HW, 64]
    float* cls_out  = out + 1 + (size_t)BATCH * A_NUM * HW * NBOX; // [M, 20]

    // Stage 1: hidden = leaky(W1 @ F + b1)
    conv_gemm<KDIM, true, true><<<dim3(25, 2, BATCH), 256>>>(features, w1, b1);
    // Stage 2: out2 = W2 @ hidden + b2
    conv_gemm<OUTCH, false, false><<<dim3(25, 1, BATCH), 256>>>(nullptr, w2, b2);
    // Head: proposals + IoU matrix
    head_kernel<<<dim3(25, A_NUM, BATCH), 128>>>(anc, bboxes, iou_out);
    // Scalar loss
    loss_kernel<<<1, 256>>>(pos_idx, neg_idx, gt_off, loss_out);
    // class_pos gather
    class_kernel<<<(MPOS * C_NUM + 255) / 256, 256>>>(pos_idx, cls_out);
}

// round 4
// speedup vs baseline: 1.7809x; 1.7809x over previous
#include <cuda_runtime.h>
#include <cuda_bf16.h>
#include <math.h>
#include <stdint.h>

#define A_NUM   9
#define C_NUM   20
#define OUTCH   65
#define BATCH   32
#define KDIM    256
#define HH      56
#define WW      56
#define HW      3136
#define NBOX    64
#define MPOS    2048

// hidden stored TRANSPOSED [b][p][m] as split bf16 (K-major for GEMM2 B operand)
__device__ __nv_bfloat16 g_hid_hi[(size_t)BATCH * HW * KDIM];
__device__ __nv_bfloat16 g_hid_lo[(size_t)BATCH * HW * KDIM];
__device__ float         g_out2 [(size_t)BATCH * OUTCH * HW];

// SMEM layout (bytes). Rows padded to 72 bf16 = 144B -> conflict-free LDS.32.
#define ROWB     144
#define A_HI_OFF 0
#define A_LO_OFF 18432
#define B_HI_OFF 36864
#define B_LO_OFF 55296
#define SMEM_SZ  73728      // also covers transpose buf 128*129*4 = 66048

__device__ __forceinline__ void mma16816(float* c,
    uint32_t a0, uint32_t a1, uint32_t a2, uint32_t a3,
    uint32_t b0, uint32_t b1)
{
    asm volatile(
        "mma.sync.aligned.m16n8k16.row.col.f32.bf16.bf16.f32 "
        "{%0,%1,%2,%3}, {%4,%5,%6,%7}, {%8,%9}, {%0,%1,%2,%3};"
        : "+f"(c[0]), "+f"(c[1]), "+f"(c[2]), "+f"(c[3])
        : "r"(a0), "r"(a1), "r"(a2), "r"(a3), "r"(b0), "r"(b1));
}

__device__ __forceinline__ uint32_t pk2(__nv_bfloat16 a, __nv_bfloat16 b) {
    __nv_bfloat162 t; t.x = a; t.y = b;
    return *(uint32_t*)&t;
}
__device__ __forceinline__ void split1(float x, __nv_bfloat16& h, __nv_bfloat16& l) {
    h = __float2bfloat16(x);
    l = __float2bfloat16(x - __bfloat162float(h));
}

// ---------------------------------------------------------------------------
// Split-bf16 HMMA GEMM: Y[b][m][p] = act( sum_k W[m][k]*X[b][k][p] + bias[m] )
// Block tile 128x128, 8 warps (2m x 4n), warp tile 64x32, K chunks of 64.
// ---------------------------------------------------------------------------
template<int MROWS, bool FIRST>
__global__ __launch_bounds__(256, 2)
void gemm_hmma(const float* __restrict__ Xf,
               const float* __restrict__ Wm,
               const float* __restrict__ bias)
{
    extern __shared__ char smem[];
    const int b     = blockIdx.z;
    const int mBase = blockIdx.y * 128;
    const int nBase = blockIdx.x * 128;
    const int tid   = threadIdx.x;
    const int wid   = tid >> 5;
    const int lane  = tid & 31;
    const int wm    = wid >> 2;          // 0..1 : m offset wm*64
    const int wn    = wid & 3;           // 0..3 : n offset wn*32
    const int g     = lane >> 2;         // 0..7
    const int tig   = lane & 3;          // 0..3

    const float* Xb = FIRST ? (Xf + (size_t)b * KDIM * HW) : nullptr;
    const __nv_bfloat16* Hh = FIRST ? nullptr : (g_hid_hi + (size_t)b * HW * KDIM);
    const __nv_bfloat16* Hl = FIRST ? nullptr : (g_hid_lo + (size_t)b * HW * KDIM);

    float acc[4][4][4];
    #pragma unroll
    for (int i = 0; i < 4; i++)
        #pragma unroll
        for (int j = 0; j < 4; j++)
            #pragma unroll
            for (int q = 0; q < 4; q++) acc[i][j][q] = 0.f;

    #pragma unroll 1
    for (int c = 0; c < 4; c++) {
        const int k0 = c * 64;
        if (c > 0) __syncthreads();

        // ---- A chunk: W[mBase..+127][k0..+63] fp32 -> split bf16, K-major
        #pragma unroll
        for (int i = 0; i < 8; i++) {
            int e   = tid + i * 256;
            int row = e >> 4;             // 0..127
            int c4  = (e & 15) * 4;       // k 0..60
            float4 v = make_float4(0.f, 0.f, 0.f, 0.f);
            int gm = mBase + row;
            if (gm < MROWS) v = *(const float4*)(Wm + (size_t)gm * KDIM + k0 + c4);
            __nv_bfloat16 h0, h1, h2, h3, l0, l1, l2, l3;
            split1(v.x, h0, l0); split1(v.y, h1, l1);
            split1(v.z, h2, l2); split1(v.w, h3, l3);
            int off = row * ROWB + c4 * 2;
            *(uint2*)(smem + A_HI_OFF + off) = make_uint2(pk2(h0, h1), pk2(h2, h3));
            *(uint2*)(smem + A_LO_OFF + off) = make_uint2(pk2(l0, l1), pk2(l2, l3));
        }

        // ---- B chunk -> smem [p][k] split bf16
        if (FIRST) {
            #pragma unroll
            for (int i = 0; i < 8; i++) {
                int e  = tid + i * 256;
                int kk = e >> 5;           // 0..63
                int p4 = (e & 31) * 4;     // 0..124
                int p  = nBase + p4;
                float4 v = make_float4(0.f, 0.f, 0.f, 0.f);
                if (p < HW) v = *(const float4*)(Xb + (size_t)(k0 + kk) * HW + p);
                float xs[4] = {v.x, v.y, v.z, v.w};
                #pragma unroll
                for (int j = 0; j < 4; j++) {
                    __nv_bfloat16 hi, lo;
                    split1(xs[j], hi, lo);
                    int off = (p4 + j) * ROWB + kk * 2;
                    *(__nv_bfloat16*)(smem + B_HI_OFF + off) = hi;
                    *(__nv_bfloat16*)(smem + B_LO_OFF + off) = lo;
                }
            }
        } else {
            #pragma unroll
            for (int i = 0; i < 8; i++) {
                int e   = tid + i * 256;
                int row = e >> 4;          // p local 0..127
                int c8  = e & 15;          // k group (4 bf16)
                int p   = nBase + row;
                uint2 vh = make_uint2(0, 0), vl = make_uint2(0, 0);
                if (p < HW) {
                    size_t gg = (size_t)p * KDIM + k0 + c8 * 4;
                    vh = *(const uint2*)(Hh + gg);
                    vl = *(const uint2*)(Hl + gg);
                }
                int off = row * ROWB + c8 * 8;
                *(uint2*)(smem + B_HI_OFF + off) = vh;
                *(uint2*)(smem + B_LO_OFF + off) = vl;
            }
        }
        __syncthreads();

        // ---- compute: 4 k-steps of 16
        #pragma unroll 1
        for (int ks = 0; ks < 4; ks++) {
            const int ka = ks * 16 * 2 + tig * 4;     // byte offset of k within row
            uint32_t ah[4][4], bh[4][2];
            #pragma unroll
            for (int i = 0; i < 4; i++) {
                const char* base = smem + A_HI_OFF + (wm * 64 + i * 16 + g) * ROWB + ka;
                ah[i][0] = *(const uint32_t*)(base);
                ah[i][1] = *(const uint32_t*)(base + 8 * ROWB);
                ah[i][2] = *(const uint32_t*)(base + 16);
                ah[i][3] = *(const uint32_t*)(base + 8 * ROWB + 16);
            }
            #pragma unroll
            for (int j = 0; j < 4; j++) {
                const char* base = smem + B_HI_OFF + (wn * 32 + j * 8 + g) * ROWB + ka;
                bh[j][0] = *(const uint32_t*)(base);
                bh[j][1] = *(const uint32_t*)(base + 16);
            }
            #pragma unroll
            for (int i = 0; i < 4; i++)
                #pragma unroll
                for (int j = 0; j < 4; j++)
                    mma16816(acc[i][j], ah[i][0], ah[i][1], ah[i][2], ah[i][3],
                             bh[j][0], bh[j][1]);
            {   // hi * lo
                uint32_t bl[4][2];
                #pragma unroll
                for (int j = 0; j < 4; j++) {
                    const char* base = smem + B_LO_OFF + (wn * 32 + j * 8 + g) * ROWB + ka;
                    bl[j][0] = *(const uint32_t*)(base);
                    bl[j][1] = *(const uint32_t*)(base + 16);
                }
                #pragma unroll
                for (int i = 0; i < 4; i++)
                    #pragma unroll
                    for (int j = 0; j < 4; j++)
                        mma16816(acc[i][j], ah[i][0], ah[i][1], ah[i][2], ah[i][3],
                                 bl[j][0], bl[j][1]);
            }
            {   // lo * hi
                uint32_t al[4][4];
                #pragma unroll
                for (int i = 0; i < 4; i++) {
                    const char* base = smem + A_LO_OFF + (wm * 64 + i * 16 + g) * ROWB + ka;
                    al[i][0] = *(const uint32_t*)(base);
                    al[i][1] = *(const uint32_t*)(base + 8 * ROWB);
                    al[i][2] = *(const uint32_t*)(base + 16);
                    al[i][3] = *(const uint32_t*)(base + 8 * ROWB + 16);
                }
                #pragma unroll
                for (int i = 0; i < 4; i++)
                    #pragma unroll
                    for (int j = 0; j < 4; j++)
                        mma16816(acc[i][j], al[i][0], al[i][1], al[i][2], al[i][3],
                                 bh[j][0], bh[j][1]);
            }
        }
    }

    // ---- epilogue ----
    if (FIRST) {
        // bias + leaky, split to bf16 pair, transpose via SMEM, store [p][m]
        __syncthreads();
        uint32_t* S = (uint32_t*)smem;          // S[p][m], stride 129
        #pragma unroll
        for (int i = 0; i < 4; i++) {
            int m0 = wm * 64 + i * 16 + g;
            float bv0 = bias[mBase + m0];
            float bv1 = bias[mBase + m0 + 8];
            #pragma unroll
            for (int j = 0; j < 4; j++) {
                int n0 = wn * 32 + j * 8 + tig * 2;
                #pragma unroll
                for (int q = 0; q < 4; q++) {
                    int mm = m0 + (q >= 2 ? 8 : 0);
                    int nn = n0 + (q & 1);
                    float h = acc[i][j][q] + ((q >= 2) ? bv1 : bv0);
                    h = (h >= 0.f) ? h : 0.01f * h;
                    __nv_bfloat16 hi, lo;
                    split1(h, hi, lo);
                    S[nn * 129 + mm] = pk2(hi, lo);
                }
            }
        }
        __syncthreads();
        #pragma unroll 4
        for (int it = 0; it < 64; it++) {
            int idx = tid + it * 256;
            int pl  = idx >> 7;         // 0..127
            int ml  = idx & 127;
            int p   = nBase + pl;
            if (p < HW) {
                uint32_t v = S[pl * 129 + ml];
                size_t o = ((size_t)b * HW + p) * KDIM + mBase + ml;
                g_hid_hi[o] = *(__nv_bfloat16*)&v;
                g_hid_lo[o] = *((__nv_bfloat16*)&v + 1);
            }
        }
    } else {
        // direct store to g_out2[m][p] fp32
        #pragma unroll
        for (int i = 0; i < 4; i++) {
            int m0 = wm * 64 + i * 16 + g;
            #pragma unroll
            for (int r = 0; r < 2; r++) {
                int m = mBase + m0 + r * 8;
                if (m < MROWS) {
                    float bv = bias[m];
                    #pragma unroll
                    for (int j = 0; j < 4; j++) {
                        int p = nBase + wn * 32 + j * 8 + tig * 2;
                        if (p < HW) {
                            float2 v;
                            v.x = acc[i][j][r * 2 + 0] + bv;
                            v.y = acc[i][j][r * 2 + 1] + bv;
                            *(float2*)(g_out2 + ((size_t)b * OUTCH + m) * HW + p) = v;
                        }
                    }
                }
            }
        }
    }
}

// ---------------------------------------------------------------------------
// Head: proposals + IoU. Warp covers 32 boxes of one pixel -> coalesced stores.
// ---------------------------------------------------------------------------
__global__ __launch_bounds__(256)
void head_kernel(const float* __restrict__ anc,
                 const float* __restrict__ bboxes,
                 float* __restrict__ iou_out)
{
    __shared__ float bx1[NBOX], by1[NBOX], bx2[NBOX], by2[NBOX], ga[NBOX];
    const int b = blockIdx.z;
    const int a = blockIdx.y;
    const int tid  = threadIdx.x;
    const int wid  = tid >> 5;
    const int lane = tid & 31;

    if (tid < NBOX) {
        const float* bb = bboxes + ((size_t)b * NBOX + tid) * 5;
        float x1 = bb[0], y1 = bb[1], x2 = bb[2], y2 = bb[3];
        bx1[tid] = x1; by1[tid] = y1; bx2[tid] = x2; by2[tid] = y2;
        ga[tid] = (x2 - x1) * (y2 - y1);
    }
    __syncthreads();

    const float wa = anc[a * 2 + 0], ha = anc[a * 2 + 1];
    const float* o = g_out2 + (size_t)b * OUTCH * HW;
    const int pBase = blockIdx.x * 128 + wid * 16;

    for (int q = 0; q < 16; q++) {
        int p = pBase + q;
        if (p >= HW) break;
        float tx = o[(5 * a + 1) * HW + p];
        float ty = o[(5 * a + 2) * HW + p];
        float tw = o[(5 * a + 3) * HW + p];
        float th = o[(5 * a + 4) * HW + p];
        int h = p / WW, w = p % WW;
        float cx = (w + 0.5f) + tx;
        float cy = (h + 0.5f) + ty;
        float nw = wa * expf(tw);
        float nh = ha * expf(th);
        float px1 = cx - nw * 0.5f, px2 = cx + nw * 0.5f;
        float py1 = cy - nh * 0.5f, py2 = cy + nh * 0.5f;
        float parea = (px2 - px1) * (py2 - py1);

        float* orow = iou_out + (((size_t)b * A_NUM + a) * HW + p) * NBOX;
        #pragma unroll
        for (int gg = 0; gg < 2; gg++) {
            int g = lane + gg * 32;
            float ix1 = fmaxf(px1, bx1[g]);
            float iy1 = fmaxf(py1, by1[g]);
            float ix2 = fminf(px2, bx2[g]);
            float iy2 = fminf(py2, by2[g]);
            float inter = fmaxf(ix2 - ix1, 0.f) * fmaxf(iy2 - iy1, 0.f);
            orow[g] = inter / (ga[g] + parea - inter);
        }
    }
}

// ---------------------------------------------------------------------------
__global__ __launch_bounds__(1024)
void loss_kernel(const int* __restrict__ pos_idx,
                 const int* __restrict__ neg_idx,
                 const float* __restrict__ gt_off,
                 float* __restrict__ out0)
{
    __shared__ float red[1024];
    const int tid = threadIdx.x;
    float s = 0.f;

    for (int m = tid; m < MPOS; m += 1024) {
        int idx = pos_idx[m];
        int b   = idx / (A_NUM * HW);
        int rem = idx % (A_NUM * HW);
        int a   = rem / HW;
        int p   = rem % HW;
        const float* o = g_out2 + ((size_t)b * OUTCH + 5 * a) * HW + p;
        float c  = o[0];
        float sc = 1.f / (1.f + expf(-c));
        float d  = sc - 1.f;
        s += 0.5f * d * d;
        #pragma unroll
        for (int k = 0; k < 4; k++) {
            float dd = o[(size_t)(1 + k) * HW] - gt_off[m * 4 + k];
            s += dd * dd;
        }
        int nidx = neg_idx[m];
        int nb   = nidx / (A_NUM * HW);
        int nrem = nidx % (A_NUM * HW);
        int na   = nrem / HW;
        int np   = nrem % HW;
        float nc = g_out2[((size_t)nb * OUTCH + 5 * na) * HW + np];
        float nsc = 1.f / (1.f + expf(-nc));
        s += 0.5f * nsc * nsc;
    }

    red[tid] = s;
    __syncthreads();
    for (int st = 512; st > 0; st >>= 1) {
        if (tid < st) red[tid] += red[tid + st];
        __syncthreads();
    }
    if (tid == 0) out0[0] = red[0] / (float)MPOS;
}

// ---------------------------------------------------------------------------
__global__ __launch_bounds__(256)
void class_kernel(const int* __restrict__ pos_idx,
                  float* __restrict__ out_cls)
{
    int t = blockIdx.x * blockDim.x + threadIdx.x;
    if (t >= MPOS * C_NUM) return;
    int m = t / C_NUM;
    int c = t % C_NUM;
    int idx = pos_idx[m];
    int b = idx / (A_NUM * HW);
    int p = idx % HW;
    out_cls[t] = g_out2[((size_t)b * OUTCH + 5 * A_NUM + c) * HW + p];
}

// ---------------------------------------------------------------------------
extern "C" void kernel_launch(void* const* d_in, const int* in_sizes, int n_in,
                              void* d_out, int out_size)
{
    const float* features = (const float*)d_in[0];
    const float* w1       = (const float*)d_in[1];
    const float* b1       = (const float*)d_in[2];
    const float* w2       = (const float*)d_in[3];
    const float* b2       = (const float*)d_in[4];
    const float* anc      = (const float*)d_in[5];
    const float* bboxes   = (const float*)d_in[7];
    const float* gt_off   = (const float*)d_in[8];
    const int*   pos_idx  = (const int*)d_in[9];
    const int*   neg_idx  = (const int*)d_in[10];

    float* out      = (float*)d_out;
    float* loss_out = out;
    float* iou_out  = out + 1;
    float* cls_out  = out + 1 + (size_t)BATCH * A_NUM * HW * NBOX;

    static bool attr_done = false;
    if (!attr_done) {
        cudaFuncSetAttribute(gemm_hmma<KDIM, true>,
                             cudaFuncAttributeMaxDynamicSharedMemorySize, SMEM_SZ);
        cudaFuncSetAttribute(gemm_hmma<OUTCH, false>,
                             cudaFuncAttributeMaxDynamicSharedMemorySize, SMEM_SZ);
        attr_done = true;
    }

    gemm_hmma<KDIM, true><<<dim3(25, 2, BATCH), 256, SMEM_SZ>>>(features, w1, b1);
    gemm_hmma<OUTCH, false><<<dim3(25, 1, BATCH), 256, SMEM_SZ>>>(nullptr, w2, b2);
    head_kernel<<<dim3(25, A_NUM, BATCH), 256>>>(anc, bboxes, iou_out);
    loss_kernel<<<1, 1024>>>(pos_idx, neg_idx, gt_off, loss_out);
    class_kernel<<<(MPOS * C_NUM + 255) / 256, 256>>>(pos_idx, cls_out);
}

// round 5
// speedup vs baseline: 2.1381x; 1.2006x over previous
#include <cuda_runtime.h>
#include <cuda_bf16.h>
#include <math.h>
#include <stdint.h>

#define A_NUM   9
#define C_NUM   20
#define OUTCH   65
#define BATCH   32
#define KDIM    256
#define HH      56
#define WW      56
#define HW      3136
#define NBOX    64
#define MPOS    2048

// ---- global scratch (no cudaMalloc allowed) ----
__device__ __nv_bfloat16 g_w1_hi[KDIM * KDIM];
__device__ __nv_bfloat16 g_w1_lo[KDIM * KDIM];
__device__ __nv_bfloat16 g_w2_hi[OUTCH * KDIM];
__device__ __nv_bfloat16 g_w2_lo[OUTCH * KDIM];
__device__ __nv_bfloat16 g_feat_hi[(size_t)BATCH * KDIM * HW];
__device__ __nv_bfloat16 g_feat_lo[(size_t)BATCH * KDIM * HW];
__device__ __nv_bfloat16 g_hid_hi[(size_t)BATCH * KDIM * HW];   // [b][m][p]
__device__ __nv_bfloat16 g_hid_lo[(size_t)BATCH * KDIM * HW];
__device__ float         g_out2 [(size_t)BATCH * OUTCH * HW];   // [b][m][p]
__device__ float         g_loss_part[32];

// ---- helpers ----
__device__ __forceinline__ uint32_t smem_u32(const void* p) {
    uint32_t a;
    asm("{ .reg .u64 t; cvta.to.shared.u64 t, %1; cvt.u32.u64 %0, t; }"
        : "=r"(a) : "l"(p));
    return a;
}
__device__ __forceinline__ uint32_t pk2(__nv_bfloat16 a, __nv_bfloat16 b) {
    __nv_bfloat162 t; t.x = a; t.y = b;
    return *(uint32_t*)&t;
}
__device__ __forceinline__ void split1(float x, __nv_bfloat16& h, __nv_bfloat16& l) {
    h = __float2bfloat16(x);
    l = __float2bfloat16(x - __bfloat162float(h));
}
__device__ __forceinline__ void mma16816(float* c,
    const uint32_t* a, uint32_t b0, uint32_t b1)
{
    asm volatile(
        "mma.sync.aligned.m16n8k16.row.col.f32.bf16.bf16.f32 "
        "{%0,%1,%2,%3}, {%4,%5,%6,%7}, {%8,%9}, {%0,%1,%2,%3};"
        : "+f"(c[0]), "+f"(c[1]), "+f"(c[2]), "+f"(c[3])
        : "r"(a[0]), "r"(a[1]), "r"(a[2]), "r"(a[3]), "r"(b0), "r"(b1));
}
__device__ __forceinline__ void ldmx4(uint32_t* r, uint32_t addr) {
    asm volatile("ldmatrix.sync.aligned.m8n8.x4.shared.b16 {%0,%1,%2,%3}, [%4];"
        : "=r"(r[0]), "=r"(r[1]), "=r"(r[2]), "=r"(r[3]) : "r"(addr));
}
__device__ __forceinline__ void ldmx4t(uint32_t* r, uint32_t addr) {
    asm volatile("ldmatrix.sync.aligned.m8n8.x4.trans.shared.b16 {%0,%1,%2,%3}, [%4];"
        : "=r"(r[0]), "=r"(r[1]), "=r"(r[2]), "=r"(r[3]) : "r"(addr));
}
__device__ __forceinline__ void cpa16(uint32_t dst, const void* src, bool ok) {
    uint32_t sz = ok ? 16u : 0u;
    asm volatile("cp.async.cg.shared.global [%0], [%1], 16, %2;"
                 :: "r"(dst), "l"(src), "r"(sz));
}
__device__ __forceinline__ void cpa_commit() {
    asm volatile("cp.async.commit_group;" ::: "memory");
}
__device__ __forceinline__ void cpa_wait2() {
    asm volatile("cp.async.wait_group 2;" ::: "memory");
}

// ---- SMEM layout: BK=32. A tile [m 128][k 32] pitch 80B; B tile [k 32][p 128] pitch 272B.
#define APITCH  80
#define BPITCH  272
#define AHI_OFF 0
#define ALO_OFF 10240
#define BHI_OFF 20480
#define BLO_OFF 29184
#define STAGE   37888
#define NSTAGE  3
#define GEMM_SMEM (STAGE * NSTAGE)     // 113664

// ---------------------------------------------------------------------------
// Pre-pass: split fp32 -> bf16 hi/lo (elementwise, float4 granular)
// ---------------------------------------------------------------------------
__global__ __launch_bounds__(256)
void convert_split(const float* __restrict__ src,
                   __nv_bfloat16* __restrict__ hi,
                   __nv_bfloat16* __restrict__ lo, int n4)
{
    int t = blockIdx.x * blockDim.x + threadIdx.x;
    if (t >= n4) return;
    float4 v = ((const float4*)src)[t];
    __nv_bfloat16 h0, h1, h2, h3, l0, l1, l2, l3;
    split1(v.x, h0, l0); split1(v.y, h1, l1);
    split1(v.z, h2, l2); split1(v.w, h3, l3);
    ((uint2*)hi)[t] = make_uint2(pk2(h0, h1), pk2(h2, h3));
    ((uint2*)lo)[t] = make_uint2(pk2(l0, l1), pk2(l2, l3));
}

// ---------------------------------------------------------------------------
// Pipelined split-bf16 HMMA GEMM.
// Block tile 128(m) x 128(p), K chunks of 32, 3-stage cp.async pipeline.
// 512 threads, 16 warps (4m x 4n), warp tile 32x32.
// A global: [m][k] bf16 pair (WROWS rows). B global: [b][k][p] bf16 pair.
// FIRST: out -> g_hid_{hi,lo}[b][m][p] (bias+leaky+split)
// else : out -> g_out2[b][m][p] fp32 (bias), rows < MROWS
// ---------------------------------------------------------------------------
template<int MROWS, bool FIRST>
__global__ __launch_bounds__(512, 1)
void gemm_pipe(const __nv_bfloat16* __restrict__ Ahi_g,
               const __nv_bfloat16* __restrict__ Alo_g,
               const __nv_bfloat16* __restrict__ Bhi_g,
               const __nv_bfloat16* __restrict__ Blo_g,
               const float* __restrict__ bias)
{
    extern __shared__ char smem[];
    const uint32_t sb = smem_u32(smem);

    const int b     = blockIdx.z;
    const int mBase = blockIdx.y * 128;
    const int nBase = blockIdx.x * 128;
    const int tid   = threadIdx.x;
    const int wid   = tid >> 5;
    const int lane  = tid & 31;
    const int wm    = wid >> 2;            // 0..3
    const int wn    = wid & 3;             // 0..3

    const size_t bofs = (size_t)b * KDIM * HW;

    // loader indices (fixed per thread)
    const int aRow = tid >> 2;             // 0..127
    const int aC   = tid & 3;              // 16B chunk within 64B row
    const bool aOk = (mBase + aRow) < MROWS;
    const int bRow = tid >> 4;             // 0..31 (k)
    const int bC   = tid & 15;             // 16B chunk within 256B row
    const int bP   = nBase + bC * 8;
    const bool bOk = bP < HW;

    const __nv_bfloat16* aSrcHi = Ahi_g + (aOk ? ((size_t)(mBase + aRow) * KDIM + aC * 8) : 0);
    const __nv_bfloat16* aSrcLo = Alo_g + (aOk ? ((size_t)(mBase + aRow) * KDIM + aC * 8) : 0);
    const __nv_bfloat16* bSrcHi = Bhi_g + bofs + (bOk ? ((size_t)bRow * HW + bP) : 0);
    const __nv_bfloat16* bSrcLo = Blo_g + bofs + (bOk ? ((size_t)bRow * HW + bP) : 0);
    const uint32_t aDst = aRow * APITCH + aC * 16;
    const uint32_t bDst = bRow * BPITCH + bC * 16;

    float acc[2][4][4];
    #pragma unroll
    for (int i = 0; i < 2; i++)
        #pragma unroll
        for (int j = 0; j < 4; j++)
            #pragma unroll
            for (int q = 0; q < 4; q++) acc[i][j][q] = 0.f;

    // prologue: 3 stages in flight
    #pragma unroll
    for (int s = 0; s < NSTAGE; s++) {
        uint32_t st = sb + s * STAGE;
        int koff = s * 32;                 // elements
        cpa16(st + AHI_OFF + aDst, aSrcHi + koff, aOk);
        cpa16(st + ALO_OFF + aDst, aSrcLo + koff, aOk);
        cpa16(st + BHI_OFF + bDst, bSrcHi + (size_t)koff * HW, bOk);
        cpa16(st + BLO_OFF + bDst, bSrcLo + (size_t)koff * HW, bOk);
        cpa_commit();
    }

    // fragment address components
    const int lane15 = lane & 15;
    const int laneHi = lane >> 4;                  // 0/1
    const int kB     = (lane >> 3) & 1;
    const int lane7  = lane & 7;
    const uint32_t aFragBase = (wm * 32 + lane15) * APITCH + laneHi * 16;
    const uint32_t bFragRow  = kB * 8 + lane7;     // + ks*16
    const uint32_t bFragCol  = (wn * 32 + laneHi * 8) * 2;

    #pragma unroll 1
    for (int c = 0; c < 8; c++) {
        cpa_wait2();
        __syncthreads();
        const uint32_t st = sb + (c % NSTAGE) * STAGE;

        #pragma unroll
        for (int ks = 0; ks < 2; ks++) {
            uint32_t ah[2][4], bh[4][2];
            // A hi frags (i = 0,1)
            ldmx4(ah[0], st + AHI_OFF + aFragBase + ks * 32);
            ldmx4(ah[1], st + AHI_OFF + aFragBase + 16 * APITCH + ks * 32);
            // B hi frags (j2 = 0,1 covering j pairs)
            {
                uint32_t r[4];
                ldmx4t(r, st + BHI_OFF + (ks * 16 + bFragRow) * BPITCH + bFragCol);
                bh[0][0] = r[0]; bh[0][1] = r[1]; bh[1][0] = r[2]; bh[1][1] = r[3];
                ldmx4t(r, st + BHI_OFF + (ks * 16 + bFragRow) * BPITCH + bFragCol + 32);
                bh[2][0] = r[0]; bh[2][1] = r[1]; bh[3][0] = r[2]; bh[3][1] = r[3];
            }
            // hi * hi
            #pragma unroll
            for (int i = 0; i < 2; i++)
                #pragma unroll
                for (int j = 0; j < 4; j++)
                    mma16816(acc[i][j], ah[i], bh[j][0], bh[j][1]);
            // hi * lo
            {
                uint32_t bl[4][2], r[4];
                ldmx4t(r, st + BLO_OFF + (ks * 16 + bFragRow) * BPITCH + bFragCol);
                bl[0][0] = r[0]; bl[0][1] = r[1]; bl[1][0] = r[2]; bl[1][1] = r[3];
                ldmx4t(r, st + BLO_OFF + (ks * 16 + bFragRow) * BPITCH + bFragCol + 32);
                bl[2][0] = r[0]; bl[2][1] = r[1]; bl[3][0] = r[2]; bl[3][1] = r[3];
                #pragma unroll
                for (int i = 0; i < 2; i++)
                    #pragma unroll
                    for (int j = 0; j < 4; j++)
                        mma16816(acc[i][j], ah[i], bl[j][0], bl[j][1]);
            }
            // lo * hi
            {
                uint32_t al[2][4];
                ldmx4(al[0], st + ALO_OFF + aFragBase + ks * 32);
                ldmx4(al[1], st + ALO_OFF + aFragBase + 16 * APITCH + ks * 32);
                #pragma unroll
                for (int i = 0; i < 2; i++)
                    #pragma unroll
                    for (int j = 0; j < 4; j++)
                        mma16816(acc[i][j], al[i], bh[j][0], bh[j][1]);
            }
        }
        __syncthreads();
        // prefetch chunk c+3 into the stage just freed
        if (c + NSTAGE < 8) {
            uint32_t st2 = sb + ((c + NSTAGE) % NSTAGE) * STAGE;
            int koff = (c + NSTAGE) * 32;
            cpa16(st2 + AHI_OFF + aDst, aSrcHi + koff, aOk);
            cpa16(st2 + ALO_OFF + aDst, aSrcLo + koff, aOk);
            cpa16(st2 + BHI_OFF + bDst, bSrcHi + (size_t)koff * HW, bOk);
            cpa16(st2 + BLO_OFF + bDst, bSrcLo + (size_t)koff * HW, bOk);
        }
        cpa_commit();
    }

    // ---- epilogue ----
    const int g   = lane >> 2;
    const int tig = lane & 3;
    #pragma unroll
    for (int i = 0; i < 2; i++) {
        const int m0 = mBase + wm * 32 + i * 16 + g;
        if (FIRST) {
            const float bv0 = bias[m0];
            const float bv1 = bias[m0 + 8];
            #pragma unroll
            for (int j = 0; j < 4; j++) {
                int p = nBase + wn * 32 + j * 8 + tig * 2;
                if (p < HW) {
                    float f0 = acc[i][j][0] + bv0; f0 = f0 >= 0.f ? f0 : 0.01f * f0;
                    float f1 = acc[i][j][1] + bv0; f1 = f1 >= 0.f ? f1 : 0.01f * f1;
                    float f2 = acc[i][j][2] + bv1; f2 = f2 >= 0.f ? f2 : 0.01f * f2;
                    float f3 = acc[i][j][3] + bv1; f3 = f3 >= 0.f ? f3 : 0.01f * f3;
                    __nv_bfloat16 h0, h1, h2, h3, l0, l1, l2, l3;
                    split1(f0, h0, l0); split1(f1, h1, l1);
                    split1(f2, h2, l2); split1(f3, h3, l3);
                    size_t o0 = bofs + (size_t)m0 * HW + p;
                    size_t o1 = bofs + (size_t)(m0 + 8) * HW + p;
                    *(uint32_t*)&g_hid_hi[o0] = pk2(h0, h1);
                    *(uint32_t*)&g_hid_lo[o0] = pk2(l0, l1);
                    *(uint32_t*)&g_hid_hi[o1] = pk2(h2, h3);
                    *(uint32_t*)&g_hid_lo[o1] = pk2(l2, l3);
                }
            }
        } else {
            const bool ok0 = m0 < MROWS;
            const bool ok1 = (m0 + 8) < MROWS;
            const float bv0 = ok0 ? bias[m0] : 0.f;
            const float bv1 = ok1 ? bias[m0 + 8] : 0.f;
            #pragma unroll
            for (int j = 0; j < 4; j++) {
                int p = nBase + wn * 32 + j * 8 + tig * 2;
                if (p < HW) {
                    if (ok0) {
                        float2 v = make_float2(acc[i][j][0] + bv0, acc[i][j][1] + bv0);
                        *(float2*)&g_out2[((size_t)b * OUTCH + m0) * HW + p] = v;
                    }
                    if (ok1) {
                        float2 v = make_float2(acc[i][j][2] + bv1, acc[i][j][3] + bv1);
                        *(float2*)&g_out2[((size_t)b * OUTCH + m0 + 8) * HW + p] = v;
                    }
                }
            }
        }
    }
}

// ---------------------------------------------------------------------------
// Head: proposals + IoU. Warp covers 32 boxes of one pixel -> coalesced stores.
// ---------------------------------------------------------------------------
__global__ __launch_bounds__(256)
void head_kernel(const float* __restrict__ anc,
                 const float* __restrict__ bboxes,
                 float* __restrict__ iou_out)
{
    __shared__ float bx1[NBOX], by1[NBOX], bx2[NBOX], by2[NBOX], ga[NBOX];
    const int b = blockIdx.z;
    const int a = blockIdx.y;
    const int tid  = threadIdx.x;
    const int wid  = tid >> 5;
    const int lane = tid & 31;

    if (tid < NBOX) {
        const float* bb = bboxes + ((size_t)b * NBOX + tid) * 5;
        float x1 = bb[0], y1 = bb[1], x2 = bb[2], y2 = bb[3];
        bx1[tid] = x1; by1[tid] = y1; bx2[tid] = x2; by2[tid] = y2;
        ga[tid] = (x2 - x1) * (y2 - y1);
    }
    __syncthreads();

    const float wa = anc[a * 2 + 0], ha = anc[a * 2 + 1];
    const float* o = g_out2 + (size_t)b * OUTCH * HW;
    const int pBase = blockIdx.x * 128 + wid * 16;

    for (int q = 0; q < 16; q++) {
        int p = pBase + q;
        if (p >= HW) break;
        float tx = o[(5 * a + 1) * HW + p];
        float ty = o[(5 * a + 2) * HW + p];
        float tw = o[(5 * a + 3) * HW + p];
        float th = o[(5 * a + 4) * HW + p];
        int h = p / WW, w = p % WW;
        float cx = (w + 0.5f) + tx;
        float cy = (h + 0.5f) + ty;
        float nw = wa * expf(tw);
        float nh = ha * expf(th);
        float px1 = cx - nw * 0.5f, px2 = cx + nw * 0.5f;
        float py1 = cy - nh * 0.5f, py2 = cy + nh * 0.5f;
        float parea = (px2 - px1) * (py2 - py1);

        float* orow = iou_out + (((size_t)b * A_NUM + a) * HW + p) * NBOX;
        #pragma unroll
        for (int gg = 0; gg < 2; gg++) {
            int gi = lane + gg * 32;
            float ix1 = fmaxf(px1, bx1[gi]);
            float iy1 = fmaxf(py1, by1[gi]);
            float ix2 = fminf(px2, bx2[gi]);
            float iy2 = fminf(py2, by2[gi]);
            float inter = fmaxf(ix2 - ix1, 0.f) * fmaxf(iy2 - iy1, 0.f);
            orow[gi] = inter / (ga[gi] + parea - inter);
        }
    }
}

// ---------------------------------------------------------------------------
// Loss: 32 partial blocks + deterministic final sum
// ---------------------------------------------------------------------------
__global__ __launch_bounds__(64)
void loss_part(const int* __restrict__ pos_idx,
               const int* __restrict__ neg_idx,
               const float* __restrict__ gt_off)
{
    __shared__ float red[64];
    const int tid = threadIdx.x;
    const int m   = blockIdx.x * 64 + tid;
    float s = 0.f;
    {
        int idx = pos_idx[m];
        int b   = idx / (A_NUM * HW);
        int rem = idx % (A_NUM * HW);
        int a   = rem / HW;
        int p   = rem % HW;
        const float* o = g_out2 + ((size_t)b * OUTCH + 5 * a) * HW + p;
        float c  = o[0];
        float sc = 1.f / (1.f + expf(-c));
        float d  = sc - 1.f;
        s += 0.5f * d * d;
        #pragma unroll
        for (int k = 0; k < 4; k++) {
            float dd = o[(size_t)(1 + k) * HW] - gt_off[m * 4 + k];
            s += dd * dd;
        }
        int nidx = neg_idx[m];
        int nb   = nidx / (A_NUM * HW);
        int nrem = nidx % (A_NUM * HW);
        int na   = nrem / HW;
        int np   = nrem % HW;
        float nc = g_out2[((size_t)nb * OUTCH + 5 * na) * HW + np];
        float nsc = 1.f / (1.f + expf(-nc));
        s += 0.5f * nsc * nsc;
    }
    red[tid] = s;
    __syncthreads();
    for (int st = 32; st > 0; st >>= 1) {
        if (tid < st) red[tid] += red[tid + st];
        __syncthreads();
    }
    if (tid == 0) g_loss_part[blockIdx.x] = red[0];
}

__global__ void loss_final(float* __restrict__ out0)
{
    float s = 0.f;
    #pragma unroll
    for (int i = 0; i < 32; i++) s += g_loss_part[i];
    out0[0] = s / (float)MPOS;
}

// ---------------------------------------------------------------------------
__global__ __launch_bounds__(256)
void class_kernel(const int* __restrict__ pos_idx,
                  float* __restrict__ out_cls)
{
    int t = blockIdx.x * blockDim.x + threadIdx.x;
    if (t >= MPOS * C_NUM) return;
    int m = t / C_NUM;
    int c = t % C_NUM;
    int idx = pos_idx[m];
    int b = idx / (A_NUM * HW);
    int p = idx % HW;
    out_cls[t] = g_out2[((size_t)b * OUTCH + 5 * A_NUM + c) * HW + p];
}

// ---------------------------------------------------------------------------
extern "C" void kernel_launch(void* const* d_in, const int* in_sizes, int n_in,
                              void* d_out, int out_size)
{
    const float* features = (const float*)d_in[0];
    const float* w1       = (const float*)d_in[1];
    const float* b1       = (const float*)d_in[2];
    const float* w2       = (const float*)d_in[3];
    const float* b2       = (const float*)d_in[4];
    const float* anc      = (const float*)d_in[5];
    const float* bboxes   = (const float*)d_in[7];
    const float* gt_off   = (const float*)d_in[8];
    const int*   pos_idx  = (const int*)d_in[9];
    const int*   neg_idx  = (const int*)d_in[10];

    float* out      = (float*)d_out;
    float* loss_out = out;
    float* iou_out  = out + 1;
    float* cls_out  = out + 1 + (size_t)BATCH * A_NUM * HW * NBOX;

    cudaFuncSetAttribute(gemm_pipe<KDIM, true>,
                         cudaFuncAttributeMaxDynamicSharedMemorySize, GEMM_SMEM);
    cudaFuncSetAttribute(gemm_pipe<OUTCH, false>,
                         cudaFuncAttributeMaxDynamicSharedMemorySize, GEMM_SMEM);

    // resolve device-global addresses (host-side, capturable)
    __nv_bfloat16 *w1h, *w1l, *w2h, *w2l, *fh, *fl, *hh, *hl;
    cudaGetSymbolAddress((void**)&w1h, g_w1_hi);
    cudaGetSymbolAddress((void**)&w1l, g_w1_lo);
    cudaGetSymbolAddress((void**)&w2h, g_w2_hi);
    cudaGetSymbolAddress((void**)&w2l, g_w2_lo);
    cudaGetSymbolAddress((void**)&fh,  g_feat_hi);
    cudaGetSymbolAddress((void**)&fl,  g_feat_lo);
    cudaGetSymbolAddress((void**)&hh,  g_hid_hi);
    cudaGetSymbolAddress((void**)&hl,  g_hid_lo);

    // pre-pass conversions
    convert_split<<<(KDIM * KDIM / 4 + 255) / 256, 256>>>(w1, w1h, w1l, KDIM * KDIM / 4);
    convert_split<<<(OUTCH * KDIM / 4 + 255) / 256, 256>>>(w2, w2h, w2l, OUTCH * KDIM / 4);
    {
        int n4 = (int)((size_t)BATCH * KDIM * HW / 4);
        convert_split<<<(n4 + 255) / 256, 256>>>(features, fh, fl, n4);
    }

    // GEMM1: hidden = leaky(W1 @ F + b1), stored split [b][m][p]
    gemm_pipe<KDIM, true><<<dim3(25, 2, BATCH), 512, GEMM_SMEM>>>(w1h, w1l, fh, fl, b1);
    // GEMM2: out2 = W2 @ hidden + b2
    gemm_pipe<OUTCH, false><<<dim3(25, 1, BATCH), 512, GEMM_SMEM>>>(w2h, w2l, hh, hl, b2);

    head_kernel<<<dim3(25, A_NUM, BATCH), 256>>>(anc, bboxes, iou_out);
    loss_part<<<32, 64>>>(pos_idx, neg_idx, gt_off);
    loss_final<<<1, 1>>>(loss_out);
    class_kernel<<<(MPOS * C_NUM + 255) / 256, 256>>>(pos_idx, cls_out);
}

// round 8
// speedup vs baseline: 2.3771x; 1.1118x over previous
#include <cuda_runtime.h>
#include <cuda_bf16.h>
#include <math.h>
#include <stdint.h>

#define A_NUM   9
#define C_NUM   20
#define OUTCH   65
#define BATCH   32
#define KDIM    256
#define HH      56
#define WW      56
#define HW      3136
#define NBOX    64
#define MPOS    2048

// ---- global scratch ----
__device__ __nv_bfloat16 g_w1_hi[KDIM * KDIM];
__device__ __nv_bfloat16 g_w1_lo[KDIM * KDIM];
__device__ __nv_bfloat16 g_w2_hi[OUTCH * KDIM];
__device__ __nv_bfloat16 g_w2_lo[OUTCH * KDIM];
__device__ __nv_bfloat16 g_feat_hi[(size_t)BATCH * KDIM * HW];
__device__ __nv_bfloat16 g_feat_lo[(size_t)BATCH * KDIM * HW];
__device__ __nv_bfloat16 g_hid_hi[(size_t)BATCH * KDIM * HW];   // [b][m][p]
__device__ __nv_bfloat16 g_hid_lo[(size_t)BATCH * KDIM * HW];
__device__ float         g_out2 [(size_t)BATCH * OUTCH * HW];   // [b][m][p]
__device__ float         g_loss_part[32];

// ---- helpers ----
__device__ __forceinline__ uint32_t smem_u32(const void* p) {
    uint32_t a;
    asm("{ .reg .u64 t; cvta.to.shared.u64 t, %1; cvt.u32.u64 %0, t; }"
        : "=r"(a) : "l"(p));
    return a;
}
__device__ __forceinline__ uint32_t pk2(__nv_bfloat16 a, __nv_bfloat16 b) {
    __nv_bfloat162 t; t.x = a; t.y = b;
    return *(uint32_t*)&t;
}
__device__ __forceinline__ void split1(float x, __nv_bfloat16& h, __nv_bfloat16& l) {
    h = __float2bfloat16(x);
    l = __float2bfloat16(x - __bfloat162float(h));
}
__device__ __forceinline__ void mma16816(float* c,
    const uint32_t* a, uint32_t b0, uint32_t b1)
{
    asm volatile(
        "mma.sync.aligned.m16n8k16.row.col.f32.bf16.bf16.f32 "
        "{%0,%1,%2,%3}, {%4,%5,%6,%7}, {%8,%9}, {%0,%1,%2,%3};"
        : "+f"(c[0]), "+f"(c[1]), "+f"(c[2]), "+f"(c[3])
        : "r"(a[0]), "r"(a[1]), "r"(a[2]), "r"(a[3]), "r"(b0), "r"(b1));
}
__device__ __forceinline__ void ldmx4(uint32_t* r, uint32_t addr) {
    asm volatile("ldmatrix.sync.aligned.m8n8.x4.shared.b16 {%0,%1,%2,%3}, [%4];"
        : "=r"(r[0]), "=r"(r[1]), "=r"(r[2]), "=r"(r[3]) : "r"(addr));
}
__device__ __forceinline__ void ldmx4t(uint32_t* r, uint32_t addr) {
    asm volatile("ldmatrix.sync.aligned.m8n8.x4.trans.shared.b16 {%0,%1,%2,%3}, [%4];"
        : "=r"(r[0]), "=r"(r[1]), "=r"(r[2]), "=r"(r[3]) : "r"(addr));
}
__device__ __forceinline__ void cpa16(uint32_t dst, const void* src, bool ok) {
    uint32_t sz = ok ? 16u : 0u;
    asm volatile("cp.async.cg.shared.global [%0], [%1], 16, %2;"
                 :: "r"(dst), "l"(src), "r"(sz));
}
__device__ __forceinline__ void cpa_commit() {
    asm volatile("cp.async.commit_group;" ::: "memory");
}
__device__ __forceinline__ void cpa_wait1() {
    asm volatile("cp.async.wait_group 1;" ::: "memory");
}

// ---- SMEM: BK=32. A [m128][k32] pitch 80B; B [k32][p64] pitch 144B.
#define APITCH  80
#define BPITCH  144
#define AHI_OFF 0
#define ALO_OFF 10240
#define BHI_OFF 20480
#define BLO_OFF 25088
#define STAGE   29696
#define NSTAGE  3
#define GEMM_SMEM (STAGE * NSTAGE)     // 89088 -> 2 CTAs/SM

// ---------------------------------------------------------------------------
__global__ __launch_bounds__(256)
void convert_split(const float* __restrict__ src,
                   __nv_bfloat16* __restrict__ hi,
                   __nv_bfloat16* __restrict__ lo, int n4)
{
    int t = blockIdx.x * blockDim.x + threadIdx.x;
    if (t >= n4) return;
    float4 v = ((const float4*)src)[t];
    __nv_bfloat16 h0, h1, h2, h3, l0, l1, l2, l3;
    split1(v.x, h0, l0); split1(v.y, h1, l1);
    split1(v.z, h2, l2); split1(v.w, h3, l3);
    ((uint2*)hi)[t] = make_uint2(pk2(h0, h1), pk2(h2, h3));
    ((uint2*)lo)[t] = make_uint2(pk2(l0, l1), pk2(l2, l3));
}

// ---------------------------------------------------------------------------
// Pipelined split-bf16 HMMA GEMM. Block tile 128m x 64p, 8 warps (4m x 2n),
// warp tile 32x32, BK=32, 3-stage cp.async, one barrier per chunk, 2 CTAs/SM.
// CORRECT ordering: wait_group -> syncthreads -> issue -> commit -> compute.
// (cp.async groups are per-thread; the barrier AFTER the wait publishes all
//  threads' completed copies before any warp reads the tile.)
// ---------------------------------------------------------------------------
template<int MROWS, bool FIRST>
__global__ __launch_bounds__(256, 2)
void gemm_pipe(const __nv_bfloat16* __restrict__ Ahi_g,
               const __nv_bfloat16* __restrict__ Alo_g,
               const __nv_bfloat16* __restrict__ Bhi_g,
               const __nv_bfloat16* __restrict__ Blo_g,
               const float* __restrict__ bias)
{
    extern __shared__ char smem[];
    const uint32_t sb = smem_u32(smem);

    const int b     = blockIdx.z;
    const int mBase = blockIdx.y * 128;
    const int nBase = blockIdx.x * 64;         // 49*64 = 3136, exact
    const int tid   = threadIdx.x;
    const int wid   = tid >> 5;
    const int lane  = tid & 31;
    const int wm    = wid >> 1;                // 0..3
    const int wn    = wid & 1;                 // 0..1

    const size_t bofs = (size_t)b * KDIM * HW;

    const int aRow0 = tid >> 2;                // 0..63
    const int aC    = tid & 3;
    const bool aOk0 = (mBase + aRow0) < MROWS;
    const bool aOk1 = (mBase + aRow0 + 64) < MROWS;
    const int bRow  = tid >> 3;                // 0..31
    const int bC    = tid & 7;
    const int bP    = nBase + bC * 8;          // always < HW

    const __nv_bfloat16* aH0 = Ahi_g + (aOk0 ? ((size_t)(mBase + aRow0) * KDIM + aC * 8) : 0);
    const __nv_bfloat16* aL0 = Alo_g + (aOk0 ? ((size_t)(mBase + aRow0) * KDIM + aC * 8) : 0);
    const __nv_bfloat16* aH1 = Ahi_g + (aOk1 ? ((size_t)(mBase + aRow0 + 64) * KDIM + aC * 8) : 0);
    const __nv_bfloat16* aL1 = Alo_g + (aOk1 ? ((size_t)(mBase + aRow0 + 64) * KDIM + aC * 8) : 0);
    const __nv_bfloat16* bH  = Bhi_g + bofs + (size_t)bRow * HW + bP;
    const __nv_bfloat16* bL  = Blo_g + bofs + (size_t)bRow * HW + bP;
    const uint32_t aD0 = aRow0 * APITCH + aC * 16;
    const uint32_t aD1 = (aRow0 + 64) * APITCH + aC * 16;
    const uint32_t bD  = bRow * BPITCH + bC * 16;

    float acc[2][4][4];
    #pragma unroll
    for (int i = 0; i < 2; i++)
        #pragma unroll
        for (int j = 0; j < 4; j++)
            #pragma unroll
            for (int q = 0; q < 4; q++) acc[i][j][q] = 0.f;

    // prologue: chunks 0,1 in flight (groups 0,1)
    #pragma unroll
    for (int s = 0; s < 2; s++) {
        uint32_t st = sb + s * STAGE;
        int ko = s * 32;
        cpa16(st + AHI_OFF + aD0, aH0 + ko, aOk0);
        cpa16(st + AHI_OFF + aD1, aH1 + ko, aOk1);
        cpa16(st + ALO_OFF + aD0, aL0 + ko, aOk0);
        cpa16(st + ALO_OFF + aD1, aL1 + ko, aOk1);
        cpa16(st + BHI_OFF + bD, bH + (size_t)ko * HW, true);
        cpa16(st + BLO_OFF + bD, bL + (size_t)ko * HW, true);
        cpa_commit();
    }

    const int lane15 = lane & 15;
    const int laneHi = lane >> 4;
    const int kB     = (lane >> 3) & 1;
    const int lane7  = lane & 7;
    const uint32_t aFragBase = (wm * 32 + lane15) * APITCH + laneHi * 16;
    const uint32_t bFragRow  = kB * 8 + lane7;
    const uint32_t bFragCol  = (wn * 32 + laneHi * 8) * 2;

    #pragma unroll 1
    for (int c = 0; c < 8; c++) {
        cpa_wait1();          // own groups: all but newest done -> chunk c resident
        __syncthreads();      // publish chunk c; orders compute(c-1) before overwrite
        if (c + 2 < 8) {
            uint32_t st2 = sb + ((c + 2) % NSTAGE) * STAGE;
            int ko = (c + 2) * 32;
            cpa16(st2 + AHI_OFF + aD0, aH0 + ko, aOk0);
            cpa16(st2 + AHI_OFF + aD1, aH1 + ko, aOk1);
            cpa16(st2 + ALO_OFF + aD0, aL0 + ko, aOk0);
            cpa16(st2 + ALO_OFF + aD1, aL1 + ko, aOk1);
            cpa16(st2 + BHI_OFF + bD, bH + (size_t)ko * HW, true);
            cpa16(st2 + BLO_OFF + bD, bL + (size_t)ko * HW, true);
        }
        cpa_commit();
        const uint32_t st = sb + (c % NSTAGE) * STAGE;

        #pragma unroll
        for (int ks = 0; ks < 2; ks++) {
            uint32_t ah[2][4], bh[4][2];
            ldmx4(ah[0], st + AHI_OFF + aFragBase + ks * 32);
            ldmx4(ah[1], st + AHI_OFF + aFragBase + 16 * APITCH + ks * 32);
            {
                uint32_t r[4];
                ldmx4t(r, st + BHI_OFF + (ks * 16 + bFragRow) * BPITCH + bFragCol);
                bh[0][0] = r[0]; bh[0][1] = r[1]; bh[1][0] = r[2]; bh[1][1] = r[3];
                ldmx4t(r, st + BHI_OFF + (ks * 16 + bFragRow) * BPITCH + bFragCol + 32);
                bh[2][0] = r[0]; bh[2][1] = r[1]; bh[3][0] = r[2]; bh[3][1] = r[3];
            }
            #pragma unroll
            for (int i = 0; i < 2; i++)
                #pragma unroll
                for (int j = 0; j < 4; j++)
                    mma16816(acc[i][j], ah[i], bh[j][0], bh[j][1]);
            {
                uint32_t bl[4][2], r[4];
                ldmx4t(r, st + BLO_OFF + (ks * 16 + bFragRow) * BPITCH + bFragCol);
                bl[0][0] = r[0]; bl[0][1] = r[1]; bl[1][0] = r[2]; bl[1][1] = r[3];
                ldmx4t(r, st + BLO_OFF + (ks * 16 + bFragRow) * BPITCH + bFragCol + 32);
                bl[2][0] = r[0]; bl[2][1] = r[1]; bl[3][0] = r[2]; bl[3][1] = r[3];
                #pragma unroll
                for (int i = 0; i < 2; i++)
                    #pragma unroll
                    for (int j = 0; j < 4; j++)
                        mma16816(acc[i][j], ah[i], bl[j][0], bl[j][1]);
            }
            {
                uint32_t al[2][4];
                ldmx4(al[0], st + ALO_OFF + aFragBase + ks * 32);
                ldmx4(al[1], st + ALO_OFF + aFragBase + 16 * APITCH + ks * 32);
                #pragma unroll
                for (int i = 0; i < 2; i++)
                    #pragma unroll
                    for (int j = 0; j < 4; j++)
                        mma16816(acc[i][j], al[i], bh[j][0], bh[j][1]);
            }
        }
    }

    // ---- epilogue ----
    const int g   = lane >> 2;
    const int tig = lane & 3;
    #pragma unroll
    for (int i = 0; i < 2; i++) {
        const int m0 = mBase + wm * 32 + i * 16 + g;
        if (FIRST) {
            const float bv0 = bias[m0];
            const float bv1 = bias[m0 + 8];
            #pragma unroll
            for (int j = 0; j < 4; j++) {
                int p = nBase + wn * 32 + j * 8 + tig * 2;
                float f0 = acc[i][j][0] + bv0; f0 = f0 >= 0.f ? f0 : 0.01f * f0;
                float f1 = acc[i][j][1] + bv0; f1 = f1 >= 0.f ? f1 : 0.01f * f1;
                float f2 = acc[i][j][2] + bv1; f2 = f2 >= 0.f ? f2 : 0.01f * f2;
                float f3 = acc[i][j][3] + bv1; f3 = f3 >= 0.f ? f3 : 0.01f * f3;
                __nv_bfloat16 h0, h1, h2, h3, l0, l1, l2, l3;
                split1(f0, h0, l0); split1(f1, h1, l1);
                split1(f2, h2, l2); split1(f3, h3, l3);
                size_t o0 = bofs + (size_t)m0 * HW + p;
                size_t o1 = bofs + (size_t)(m0 + 8) * HW + p;
                *(uint32_t*)&g_hid_hi[o0] = pk2(h0, h1);
                *(uint32_t*)&g_hid_lo[o0] = pk2(l0, l1);
                *(uint32_t*)&g_hid_hi[o1] = pk2(h2, h3);
                *(uint32_t*)&g_hid_lo[o1] = pk2(l2, l3);
            }
        } else {
            const bool ok0 = m0 < MROWS;
            const bool ok1 = (m0 + 8) < MROWS;
            const float bv0 = ok0 ? bias[m0] : 0.f;
            const float bv1 = ok1 ? bias[m0 + 8] : 0.f;
            #pragma unroll
            for (int j = 0; j < 4; j++) {
                int p = nBase + wn * 32 + j * 8 + tig * 2;
                if (ok0) {
                    float2 v = make_float2(acc[i][j][0] + bv0, acc[i][j][1] + bv0);
                    *(float2*)&g_out2[((size_t)b * OUTCH + m0) * HW + p] = v;
                }
                if (ok1) {
                    float2 v = make_float2(acc[i][j][2] + bv1, acc[i][j][3] + bv1);
                    *(float2*)&g_out2[((size_t)b * OUTCH + m0 + 8) * HW + p] = v;
                }
            }
        }
    }
}

// ---------------------------------------------------------------------------
__global__ __launch_bounds__(256)
void head_kernel(const float* __restrict__ anc,
                 const float* __restrict__ bboxes,
                 float* __restrict__ iou_out)
{
    __shared__ float bx1[NBOX], by1[NBOX], bx2[NBOX], by2[NBOX], ga[NBOX];
    const int b = blockIdx.z;
    const int a = blockIdx.y;
    const int tid  = threadIdx.x;
    const int wid  = tid >> 5;
    const int lane = tid & 31;

    if (tid < NBOX) {
        const float* bb = bboxes + ((size_t)b * NBOX + tid) * 5;
        float x1 = bb[0], y1 = bb[1], x2 = bb[2], y2 = bb[3];
        bx1[tid] = x1; by1[tid] = y1; bx2[tid] = x2; by2[tid] = y2;
        ga[tid] = (x2 - x1) * (y2 - y1);
    }
    __syncthreads();

    const float wa = anc[a * 2 + 0], ha = anc[a * 2 + 1];
    const float* o = g_out2 + (size_t)b * OUTCH * HW;
    const int pBase = blockIdx.x * 128 + wid * 16;

    for (int q = 0; q < 16; q++) {
        int p = pBase + q;
        if (p >= HW) break;
        float tx = o[(5 * a + 1) * HW + p];
        float ty = o[(5 * a + 2) * HW + p];
        float tw = o[(5 * a + 3) * HW + p];
        float th = o[(5 * a + 4) * HW + p];
        int h = p / WW, w = p % WW;
        float cx = (w + 0.5f) + tx;
        float cy = (h + 0.5f) + ty;
        float nw = wa * expf(tw);
        float nh = ha * expf(th);
        float px1 = cx - nw * 0.5f, px2 = cx + nw * 0.5f;
        float py1 = cy - nh * 0.5f, py2 = cy + nh * 0.5f;
        float parea = (px2 - px1) * (py2 - py1);

        float* orow = iou_out + (((size_t)b * A_NUM + a) * HW + p) * NBOX;
        #pragma unroll
        for (int gg = 0; gg < 2; gg++) {
            int gi = lane + gg * 32;
            float ix1 = fmaxf(px1, bx1[gi]);
            float iy1 = fmaxf(py1, by1[gi]);
            float ix2 = fminf(px2, bx2[gi]);
            float iy2 = fminf(py2, by2[gi]);
            float inter = fmaxf(ix2 - ix1, 0.f) * fmaxf(iy2 - iy1, 0.f);
            orow[gi] = inter / (ga[gi] + parea - inter);
        }
    }
}

// ---------------------------------------------------------------------------
__global__ __launch_bounds__(64)
void loss_part(const int* __restrict__ pos_idx,
               const int* __restrict__ neg_idx,
               const float* __restrict__ gt_off)
{
    __shared__ float red[64];
    const int tid = threadIdx.x;
    const int m   = blockIdx.x * 64 + tid;
    float s = 0.f;
    {
        int idx = pos_idx[m];
        int b   = idx / (A_NUM * HW);
        int rem = idx % (A_NUM * HW);
        int a   = rem / HW;
        int p   = rem % HW;
        const float* o = g_out2 + ((size_t)b * OUTCH + 5 * a) * HW + p;
        float c  = o[0];
        float sc = 1.f / (1.f + expf(-c));
        float d  = sc - 1.f;
        s += 0.5f * d * d;
        #pragma unroll
        for (int k = 0; k < 4; k++) {
            float dd = o[(size_t)(1 + k) * HW] - gt_off[m * 4 + k];
            s += dd * dd;
        }
        int nidx = neg_idx[m];
        int nb   = nidx / (A_NUM * HW);
        int nrem = nidx % (A_NUM * HW);
        int na   = nrem / HW;
        int np   = nrem % HW;
        float nc = g_out2[((size_t)nb * OUTCH + 5 * na) * HW + np];
        float nsc = 1.f / (1.f + expf(-nc));
        s += 0.5f * nsc * nsc;
    }
    red[tid] = s;
    __syncthreads();
    for (int st = 32; st > 0; st >>= 1) {
        if (tid < st) red[tid] += red[tid + st];
        __syncthreads();
    }
    if (tid == 0) g_loss_part[blockIdx.x] = red[0];
}

__global__ void loss_final(float* __restrict__ out0)
{
    float s = 0.f;
    #pragma unroll
    for (int i = 0; i < 32; i++) s += g_loss_part[i];
    out0[0] = s / (float)MPOS;
}

// ---------------------------------------------------------------------------
__global__ __launch_bounds__(256)
void class_kernel(const int* __restrict__ pos_idx,
                  float* __restrict__ out_cls)
{
    int t = blockIdx.x * blockDim.x + threadIdx.x;
    if (t >= MPOS * C_NUM) return;
    int m = t / C_NUM;
    int c = t % C_NUM;
    int idx = pos_idx[m];
    int b = idx / (A_NUM * HW);
    int p = idx % HW;
    out_cls[t] = g_out2[((size_t)b * OUTCH + 5 * A_NUM + c) * HW + p];
}

// ---------------------------------------------------------------------------
extern "C" void kernel_launch(void* const* d_in, const int* in_sizes, int n_in,
                              void* d_out, int out_size)
{
    const float* features = (const float*)d_in[0];
    const float* w1       = (const float*)d_in[1];
    const float* b1       = (const float*)d_in[2];
    const float* w2       = (const float*)d_in[3];
    const float* b2       = (const float*)d_in[4];
    const float* anc      = (const float*)d_in[5];
    const float* bboxes   = (const float*)d_in[7];
    const float* gt_off   = (const float*)d_in[8];
    const int*   pos_idx  = (const int*)d_in[9];
    const int*   neg_idx  = (const int*)d_in[10];

    float* out      = (float*)d_out;
    float* loss_out = out;
    float* iou_out  = out + 1;
    float* cls_out  = out + 1 + (size_t)BATCH * A_NUM * HW * NBOX;

    cudaFuncSetAttribute(gemm_pipe<KDIM, true>,
                         cudaFuncAttributeMaxDynamicSharedMemorySize, GEMM_SMEM);
    cudaFuncSetAttribute(gemm_pipe<OUTCH, false>,
                         cudaFuncAttributeMaxDynamicSharedMemorySize, GEMM_SMEM);

    __nv_bfloat16 *w1h, *w1l, *w2h, *w2l, *fh, *fl, *hh, *hl;
    cudaGetSymbolAddress((void**)&w1h, g_w1_hi);
    cudaGetSymbolAddress((void**)&w1l, g_w1_lo);
    cudaGetSymbolAddress((void**)&w2h, g_w2_hi);
    cudaGetSymbolAddress((void**)&w2l, g_w2_lo);
    cudaGetSymbolAddress((void**)&fh,  g_feat_hi);
    cudaGetSymbolAddress((void**)&fl,  g_feat_lo);
    cudaGetSymbolAddress((void**)&hh,  g_hid_hi);
    cudaGetSymbolAddress((void**)&hl,  g_hid_lo);

    convert_split<<<(KDIM * KDIM / 4 + 255) / 256, 256>>>(w1, w1h, w1l, KDIM * KDIM / 4);
    convert_split<<<(OUTCH * KDIM / 4 + 255) / 256, 256>>>(w2, w2h, w2l, OUTCH * KDIM / 4);
    {
        int n4 = (int)((size_t)BATCH * KDIM * HW / 4);
        convert_split<<<(n4 + 255) / 256, 256>>>(features, fh, fl, n4);
    }

    gemm_pipe<KDIM, true><<<dim3(49, 2, BATCH), 256, GEMM_SMEM>>>(w1h, w1l, fh, fl, b1);
    gemm_pipe<OUTCH, false><<<dim3(49, 1, BATCH), 256, GEMM_SMEM>>>(w2h, w2l, hh, hl, b2);

    head_kernel<<<dim3(25, A_NUM, BATCH), 256>>>(anc, bboxes, iou_out);
    loss_part<<<32, 64>>>(pos_idx, neg_idx, gt_off);
    loss_final<<<1, 1>>>(loss_out);
    class_kernel<<<(MPOS * C_NUM + 255) / 256, 256>>>(pos_idx, cls_out);
}

// round 9
// speedup vs baseline: 2.4893x; 1.0472x over previous
#include <cuda_runtime.h>
#include <cuda_bf16.h>
#include <math.h>
#include <stdint.h>

#define A_NUM   9
#define C_NUM   20
#define OUTCH   65
#define BATCH   32
#define KDIM    256
#define HH      56
#define WW      56
#define HW      3136
#define NBOX    64
#define MPOS    2048

// ---- global scratch ----
__device__ __nv_bfloat16 g_w1_hi[KDIM * KDIM];
__device__ __nv_bfloat16 g_w1_lo[KDIM * KDIM];
__device__ __nv_bfloat16 g_w2_hi[OUTCH * KDIM];
__device__ __nv_bfloat16 g_w2_lo[OUTCH * KDIM];
__device__ __nv_bfloat16 g_feat_hi[(size_t)BATCH * KDIM * HW];
__device__ __nv_bfloat16 g_feat_lo[(size_t)BATCH * KDIM * HW];
__device__ __nv_bfloat16 g_hid_hi[(size_t)BATCH * KDIM * HW];   // [b][m][p]
__device__ __nv_bfloat16 g_hid_lo[(size_t)BATCH * KDIM * HW];
__device__ float         g_out2 [(size_t)BATCH * OUTCH * HW];   // [b][m][p]
__device__ float         g_loss_part[32];

// ---- helpers ----
__device__ __forceinline__ uint32_t smem_u32(const void* p) {
    uint32_t a;
    asm("{ .reg .u64 t; cvta.to.shared.u64 t, %1; cvt.u32.u64 %0, t; }"
        : "=r"(a) : "l"(p));
    return a;
}
__device__ __forceinline__ uint32_t pk2(__nv_bfloat16 a, __nv_bfloat16 b) {
    __nv_bfloat162 t; t.x = a; t.y = b;
    return *(uint32_t*)&t;
}
__device__ __forceinline__ void split1(float x, __nv_bfloat16& h, __nv_bfloat16& l) {
    h = __float2bfloat16(x);
    l = __float2bfloat16(x - __bfloat162float(h));
}
__device__ __forceinline__ void mma16816(float* c,
    const uint32_t* a, uint32_t b0, uint32_t b1)
{
    asm volatile(
        "mma.sync.aligned.m16n8k16.row.col.f32.bf16.bf16.f32 "
        "{%0,%1,%2,%3}, {%4,%5,%6,%7}, {%8,%9}, {%0,%1,%2,%3};"
        : "+f"(c[0]), "+f"(c[1]), "+f"(c[2]), "+f"(c[3])
        : "r"(a[0]), "r"(a[1]), "r"(a[2]), "r"(a[3]), "r"(b0), "r"(b1));
}
__device__ __forceinline__ void ldmx4(uint32_t* r, uint32_t addr) {
    asm volatile("ldmatrix.sync.aligned.m8n8.x4.shared.b16 {%0,%1,%2,%3}, [%4];"
        : "=r"(r[0]), "=r"(r[1]), "=r"(r[2]), "=r"(r[3]) : "r"(addr));
}
__device__ __forceinline__ void ldmx4t(uint32_t* r, uint32_t addr) {
    asm volatile("ldmatrix.sync.aligned.m8n8.x4.trans.shared.b16 {%0,%1,%2,%3}, [%4];"
        : "=r"(r[0]), "=r"(r[1]), "=r"(r[2]), "=r"(r[3]) : "r"(addr));
}
__device__ __forceinline__ void cpa16(uint32_t dst, const void* src, bool ok) {
    uint32_t sz = ok ? 16u : 0u;
    asm volatile("cp.async.cg.shared.global [%0], [%1], 16, %2;"
                 :: "r"(dst), "l"(src), "r"(sz));
}
__device__ __forceinline__ void cpa_commit() {
    asm volatile("cp.async.commit_group;" ::: "memory");
}
__device__ __forceinline__ void cpa_wait1() {
    asm volatile("cp.async.wait_group 1;" ::: "memory");
}

// ---- SMEM: BK=32. A [m128][k32] pitch 80B; B [k32][p128] pitch 272B.
#define APITCH  80
#define BPITCH  272
#define AHI_OFF 0
#define ALO_OFF 10240
#define BHI_OFF 20480
#define BLO_OFF 29184
#define STAGE   37888
#define NSTAGE  2
#define GEMM_SMEM (STAGE * NSTAGE)     // 75776 -> 2 CTAs/SM

// ---------------------------------------------------------------------------
__global__ __launch_bounds__(256)
void convert_split(const float* __restrict__ src,
                   __nv_bfloat16* __restrict__ hi,
                   __nv_bfloat16* __restrict__ lo, int n4)
{
    int t = blockIdx.x * blockDim.x + threadIdx.x;
    if (t >= n4) return;
    float4 v = ((const float4*)src)[t];
    __nv_bfloat16 h0, h1, h2, h3, l0, l1, l2, l3;
    split1(v.x, h0, l0); split1(v.y, h1, l1);
    split1(v.z, h2, l2); split1(v.w, h3, l3);
    ((uint2*)hi)[t] = make_uint2(pk2(h0, h1), pk2(h2, h3));
    ((uint2*)lo)[t] = make_uint2(pk2(l0, l1), pk2(l2, l3));
}

// ---------------------------------------------------------------------------
// Pipelined split-bf16 HMMA GEMM. Block tile 128m x 128p, 8 warps (2m x 4n),
// warp tile 64x32, BK=32, 2-stage cp.async, 2 CTAs/SM.
// Per chunk: wait1 -> sync -> compute(c) -> sync -> issue(c+2) -> commit.
// (cp.async groups are per-thread; barrier after wait publishes all copies.
//  Barrier between compute and issue protects WAR on buffer c%2.)
// ---------------------------------------------------------------------------
template<int MROWS, bool FIRST>
__global__ __launch_bounds__(256, 2)
void gemm_pipe(const __nv_bfloat16* __restrict__ Ahi_g,
               const __nv_bfloat16* __restrict__ Alo_g,
               const __nv_bfloat16* __restrict__ Bhi_g,
               const __nv_bfloat16* __restrict__ Blo_g,
               const float* __restrict__ bias)
{
    extern __shared__ char smem[];
    const uint32_t sb = smem_u32(smem);

    const int b     = blockIdx.z;
    const int mBase = blockIdx.y * 128;
    const int nBase = blockIdx.x * 128;        // 25 tiles, last is partial
    const int tid   = threadIdx.x;
    const int wid   = tid >> 5;
    const int lane  = tid & 31;
    const int wm    = wid >> 2;                // 0..1 (m offset wm*64)
    const int wn    = wid & 3;                 // 0..3 (n offset wn*32)

    const size_t bofs = (size_t)b * KDIM * HW;

    // A loader: 128 rows x 4 chunks of 16B -> 2 per thread
    const int aRow = tid >> 2;                 // 0..63 (+64 for second half? no: e>>2)
    // use generic e-indexing in the issue macro below
    // B loader: 32 rows x 16 chunks of 16B -> 2 per thread

    float acc[4][4][4];
    #pragma unroll
    for (int i = 0; i < 4; i++)
        #pragma unroll
        for (int j = 0; j < 4; j++)
            #pragma unroll
            for (int q = 0; q < 4; q++) acc[i][j][q] = 0.f;

    // per-thread loader coordinates
    const int aR0 = tid >> 2;                  // 0..63
    const int aC  = tid & 3;
    const bool aOk0 = (mBase + aR0) < MROWS;
    const bool aOk1 = (mBase + aR0 + 64) < MROWS;
    const int bR0 = tid >> 4;                  // 0..15
    const int bC  = tid & 15;
    const int bP  = nBase + bC * 8;
    const bool bOk = bP < HW;

    const __nv_bfloat16* aH0 = Ahi_g + (aOk0 ? ((size_t)(mBase + aR0) * KDIM + aC * 8) : 0);
    const __nv_bfloat16* aL0 = Alo_g + (aOk0 ? ((size_t)(mBase + aR0) * KDIM + aC * 8) : 0);
    const __nv_bfloat16* aH1 = Ahi_g + (aOk1 ? ((size_t)(mBase + aR0 + 64) * KDIM + aC * 8) : 0);
    const __nv_bfloat16* aL1 = Alo_g + (aOk1 ? ((size_t)(mBase + aR0 + 64) * KDIM + aC * 8) : 0);
    const __nv_bfloat16* bH0 = Bhi_g + bofs + (size_t)bR0 * HW + bP;
    const __nv_bfloat16* bL0 = Blo_g + bofs + (size_t)bR0 * HW + bP;
    const uint32_t aD0 = aR0 * APITCH + aC * 16;
    const uint32_t aD1 = (aR0 + 64) * APITCH + aC * 16;
    const uint32_t bD0 = bR0 * BPITCH + bC * 16;
    const uint32_t bD1 = (bR0 + 16) * BPITCH + bC * 16;

    #define ISSUE_CHUNK(ST, KO)                                                  \
        do {                                                                     \
            cpa16((ST) + AHI_OFF + aD0, aH0 + (KO), aOk0);                       \
            cpa16((ST) + AHI_OFF + aD1, aH1 + (KO), aOk1);                       \
            cpa16((ST) + ALO_OFF + aD0, aL0 + (KO), aOk0);                       \
            cpa16((ST) + ALO_OFF + aD1, aL1 + (KO), aOk1);                       \
            cpa16((ST) + BHI_OFF + bD0, bH0 + (size_t)(KO) * HW, bOk);           \
            cpa16((ST) + BHI_OFF + bD1, bH0 + (size_t)((KO) + 16) * HW, bOk);    \
            cpa16((ST) + BLO_OFF + bD0, bL0 + (size_t)(KO) * HW, bOk);           \
            cpa16((ST) + BLO_OFF + bD1, bL0 + (size_t)((KO) + 16) * HW, bOk);    \
        } while (0)

    // prologue: chunks 0,1
    ISSUE_CHUNK(sb, 0);
    cpa_commit();
    ISSUE_CHUNK(sb + STAGE, 32);
    cpa_commit();

    // warp-uniform m-frag validity (prunes GEMM2 padding work)
    bool vi[4];
    #pragma unroll
    for (int i = 0; i < 4; i++)
        vi[i] = FIRST ? true : ((mBase + wm * 64 + i * 16) < MROWS);

    const int lane15 = lane & 15;
    const int laneHi = lane >> 4;
    const int kB     = (lane >> 3) & 1;
    const int lane7  = lane & 7;
    const uint32_t aFragBase = (wm * 64 + lane15) * APITCH + laneHi * 16;
    const uint32_t bFragRow  = kB * 8 + lane7;
    const uint32_t bFragCol  = (wn * 32 + laneHi * 8) * 2;

    #pragma unroll 1
    for (int c = 0; c < 8; c++) {
        cpa_wait1();          // own groups: all but newest done -> chunk c resident
        __syncthreads();      // publish chunk c across all threads
        const uint32_t st = sb + (c & 1) * STAGE;

        #pragma unroll
        for (int ks = 0; ks < 2; ks++) {
            uint32_t ah[4][4], bh[4][2];
            #pragma unroll
            for (int i = 0; i < 4; i++)
                if (vi[i])
                    ldmx4(ah[i], st + AHI_OFF + aFragBase + i * 16 * APITCH + ks * 32);
            {
                uint32_t r[4];
                ldmx4t(r, st + BHI_OFF + (ks * 16 + bFragRow) * BPITCH + bFragCol);
                bh[0][0] = r[0]; bh[0][1] = r[1]; bh[1][0] = r[2]; bh[1][1] = r[3];
                ldmx4t(r, st + BHI_OFF + (ks * 16 + bFragRow) * BPITCH + bFragCol + 32);
                bh[2][0] = r[0]; bh[2][1] = r[1]; bh[3][0] = r[2]; bh[3][1] = r[3];
            }
            #pragma unroll
            for (int i = 0; i < 4; i++)
                if (vi[i])
                    #pragma unroll
                    for (int j = 0; j < 4; j++)
                        mma16816(acc[i][j], ah[i], bh[j][0], bh[j][1]);
            {
                uint32_t bl[4][2], r[4];
                ldmx4t(r, st + BLO_OFF + (ks * 16 + bFragRow) * BPITCH + bFragCol);
                bl[0][0] = r[0]; bl[0][1] = r[1]; bl[1][0] = r[2]; bl[1][1] = r[3];
                ldmx4t(r, st + BLO_OFF + (ks * 16 + bFragRow) * BPITCH + bFragCol + 32);
                bl[2][0] = r[0]; bl[2][1] = r[1]; bl[3][0] = r[2]; bl[3][1] = r[3];
                #pragma unroll
                for (int i = 0; i < 4; i++)
                    if (vi[i])
                        #pragma unroll
                        for (int j = 0; j < 4; j++)
                            mma16816(acc[i][j], ah[i], bl[j][0], bl[j][1]);
            }
            {
                uint32_t al[4];
                #pragma unroll
                for (int i = 0; i < 4; i++)
                    if (vi[i]) {
                        ldmx4(al, st + ALO_OFF + aFragBase + i * 16 * APITCH + ks * 32);
                        #pragma unroll
                        for (int j = 0; j < 4; j++)
                            mma16816(acc[i][j], al, bh[j][0], bh[j][1]);
                    }
            }
        }

        __syncthreads();      // all warps done reading buffer c&1 before refill
        if (c + 2 < 8) {
            const uint32_t st2 = sb + (c & 1) * STAGE;
            const int ko = (c + 2) * 32;
            ISSUE_CHUNK(st2, ko);
        }
        cpa_commit();
    }
    #undef ISSUE_CHUNK

    // ---- epilogue ----
    const int g   = lane >> 2;
    const int tig = lane & 3;
    #pragma unroll
    for (int i = 0; i < 4; i++) {
        const int m0 = mBase + wm * 64 + i * 16 + g;
        if (FIRST) {
            const float bv0 = bias[m0];
            const float bv1 = bias[m0 + 8];
            #pragma unroll
            for (int j = 0; j < 4; j++) {
                int p = nBase + wn * 32 + j * 8 + tig * 2;
                if (p < HW) {
                    float f0 = acc[i][j][0] + bv0; f0 = f0 >= 0.f ? f0 : 0.01f * f0;
                    float f1 = acc[i][j][1] + bv0; f1 = f1 >= 0.f ? f1 : 0.01f * f1;
                    float f2 = acc[i][j][2] + bv1; f2 = f2 >= 0.f ? f2 : 0.01f * f2;
                    float f3 = acc[i][j][3] + bv1; f3 = f3 >= 0.f ? f3 : 0.01f * f3;
                    __nv_bfloat16 h0, h1, h2, h3, l0, l1, l2, l3;
                    split1(f0, h0, l0); split1(f1, h1, l1);
                    split1(f2, h2, l2); split1(f3, h3, l3);
                    size_t o0 = bofs + (size_t)m0 * HW + p;
                    size_t o1 = bofs + (size_t)(m0 + 8) * HW + p;
                    *(uint32_t*)&g_hid_hi[o0] = pk2(h0, h1);
                    *(uint32_t*)&g_hid_lo[o0] = pk2(l0, l1);
                    *(uint32_t*)&g_hid_hi[o1] = pk2(h2, h3);
                    *(uint32_t*)&g_hid_lo[o1] = pk2(l2, l3);
                }
            }
        } else {
            const bool ok0 = m0 < MROWS;
            const bool ok1 = (m0 + 8) < MROWS;
            if (!ok0 && !ok1) continue;
            const float bv0 = ok0 ? bias[m0] : 0.f;
            const float bv1 = ok1 ? bias[m0 + 8] : 0.f;
            #pragma unroll
            for (int j = 0; j < 4; j++) {
                int p = nBase + wn * 32 + j * 8 + tig * 2;
                if (p < HW) {
                    if (ok0) {
                        float2 v = make_float2(acc[i][j][0] + bv0, acc[i][j][1] + bv0);
                        *(float2*)&g_out2[((size_t)b * OUTCH + m0) * HW + p] = v;
                    }
                    if (ok1) {
                        float2 v = make_float2(acc[i][j][2] + bv1, acc[i][j][3] + bv1);
                        *(float2*)&g_out2[((size_t)b * OUTCH + m0 + 8) * HW + p] = v;
                    }
                }
            }
        }
    }
}

// ---------------------------------------------------------------------------
__global__ __launch_bounds__(256)
void head_kernel(const float* __restrict__ anc,
                 const float* __restrict__ bboxes,
                 float* __restrict__ iou_out)
{
    __shared__ float bx1[NBOX], by1[NBOX], bx2[NBOX], by2[NBOX], ga[NBOX];
    const int b = blockIdx.z;
    const int a = blockIdx.y;
    const int tid  = threadIdx.x;
    const int wid  = tid >> 5;
    const int lane = tid & 31;

    if (tid < NBOX) {
        const float* bb = bboxes + ((size_t)b * NBOX + tid) * 5;
        float x1 = bb[0], y1 = bb[1], x2 = bb[2], y2 = bb[3];
        bx1[tid] = x1; by1[tid] = y1; bx2[tid] = x2; by2[tid] = y2;
        ga[tid] = (x2 - x1) * (y2 - y1);
    }
    __syncthreads();

    const float wa = anc[a * 2 + 0], ha = anc[a * 2 + 1];
    const float* o = g_out2 + (size_t)b * OUTCH * HW;
    const int pBase = blockIdx.x * 128 + wid * 16;

    for (int q = 0; q < 16; q++) {
        int p = pBase + q;
        if (p >= HW) break;
        float tx = o[(5 * a + 1) * HW + p];
        float ty = o[(5 * a + 2) * HW + p];
        float tw = o[(5 * a + 3) * HW + p];
        float th = o[(5 * a + 4) * HW + p];
        int h = p / WW, w = p % WW;
        float cx = (w + 0.5f) + tx;
        float cy = (h + 0.5f) + ty;
        float nw = wa * expf(tw);
        float nh = ha * expf(th);
        float px1 = cx - nw * 0.5f, px2 = cx + nw * 0.5f;
        float py1 = cy - nh * 0.5f, py2 = cy + nh * 0.5f;
        float parea = (px2 - px1) * (py2 - py1);

        float* orow = iou_out + (((size_t)b * A_NUM + a) * HW + p) * NBOX;
        #pragma unroll
        for (int gg = 0; gg < 2; gg++) {
            int gi = lane + gg * 32;
            float ix1 = fmaxf(px1, bx1[gi]);
            float iy1 = fmaxf(py1, by1[gi]);
            float ix2 = fminf(px2, bx2[gi]);
            float iy2 = fminf(py2, by2[gi]);
            float inter = fmaxf(ix2 - ix1, 0.f) * fmaxf(iy2 - iy1, 0.f);
            orow[gi] = inter / (ga[gi] + parea - inter);
        }
    }
}

// ---------------------------------------------------------------------------
__global__ __launch_bounds__(64)
void loss_part(const int* __restrict__ pos_idx,
               const int* __restrict__ neg_idx,
               const float* __restrict__ gt_off)
{
    __shared__ float red[64];
    const int tid = threadIdx.x;
    const int m   = blockIdx.x * 64 + tid;
    float s = 0.f;
    {
        int idx = pos_idx[m];
        int b   = idx / (A_NUM * HW);
        int rem = idx % (A_NUM * HW);
        int a   = rem / HW;
        int p   = rem % HW;
        const float* o = g_out2 + ((size_t)b * OUTCH + 5 * a) * HW + p;
        float c  = o[0];
        float sc = 1.f / (1.f + expf(-c));
        float d  = sc - 1.f;
        s += 0.5f * d * d;
        #pragma unroll
        for (int k = 0; k < 4; k++) {
            float dd = o[(size_t)(1 + k) * HW] - gt_off[m * 4 + k];
            s += dd * dd;
        }
        int nidx = neg_idx[m];
        int nb   = nidx / (A_NUM * HW);
        int nrem = nidx % (A_NUM * HW);
        int na   = nrem / HW;
        int np   = nrem % HW;
        float nc = g_out2[((size_t)nb * OUTCH + 5 * na) * HW + np];
        float nsc = 1.f / (1.f + expf(-nc));
        s += 0.5f * nsc * nsc;
    }
    red[tid] = s;
    __syncthreads();
    for (int st = 32; st > 0; st >>= 1) {
        if (tid < st) red[tid] += red[tid + st];
        __syncthreads();
    }
    if (tid == 0) g_loss_part[blockIdx.x] = red[0];
}

__global__ void loss_final(float* __restrict__ out0)
{
    float s = 0.f;
    #pragma unroll
    for (int i = 0; i < 32; i++) s += g_loss_part[i];
    out0[0] = s / (float)MPOS;
}

// ---------------------------------------------------------------------------
__global__ __launch_bounds__(256)
void class_kernel(const int* __restrict__ pos_idx,
                  float* __restrict__ out_cls)
{
    int t = blockIdx.x * blockDim.x + threadIdx.x;
    if (t >= MPOS * C_NUM) return;
    int m = t / C_NUM;
    int c = t % C_NUM;
    int idx = pos_idx[m];
    int b = idx / (A_NUM * HW);
    int p = idx % HW;
    out_cls[t] = g_out2[((size_t)b * OUTCH + 5 * A_NUM + c) * HW + p];
}

// ---------------------------------------------------------------------------
extern "C" void kernel_launch(void* const* d_in, const int* in_sizes, int n_in,
                              void* d_out, int out_size)
{
    const float* features = (const float*)d_in[0];
    const float* w1       = (const float*)d_in[1];
    const float* b1       = (const float*)d_in[2];
    const float* w2       = (const float*)d_in[3];
    const float* b2       = (const float*)d_in[4];
    const float* anc      = (const float*)d_in[5];
    const float* bboxes   = (const float*)d_in[7];
    const float* gt_off   = (const float*)d_in[8];
    const int*   pos_idx  = (const int*)d_in[9];
    const int*   neg_idx  = (const int*)d_in[10];

    float* out      = (float*)d_out;
    float* loss_out = out;
    float* iou_out  = out + 1;
    float* cls_out  = out + 1 + (size_t)BATCH * A_NUM * HW * NBOX;

    cudaFuncSetAttribute(gemm_pipe<KDIM, true>,
                         cudaFuncAttributeMaxDynamicSharedMemorySize, GEMM_SMEM);
    cudaFuncSetAttribute(gemm_pipe<OUTCH, false>,
                         cudaFuncAttributeMaxDynamicSharedMemorySize, GEMM_SMEM);

    __nv_bfloat16 *w1h, *w1l, *w2h, *w2l, *fh, *fl, *hh, *hl;
    cudaGetSymbolAddress((void**)&w1h, g_w1_hi);
    cudaGetSymbolAddress((void**)&w1l, g_w1_lo);
    cudaGetSymbolAddress((void**)&w2h, g_w2_hi);
    cudaGetSymbolAddress((void**)&w2l, g_w2_lo);
    cudaGetSymbolAddress((void**)&fh,  g_feat_hi);
    cudaGetSymbolAddress((void**)&fl,  g_feat_lo);
    cudaGetSymbolAddress((void**)&hh,  g_hid_hi);
    cudaGetSymbolAddress((void**)&hl,  g_hid_lo);

    convert_split<<<(KDIM * KDIM / 4 + 255) / 256, 256>>>(w1, w1h, w1l, KDIM * KDIM / 4);
    convert_split<<<(OUTCH * KDIM / 4 + 255) / 256, 256>>>(w2, w2h, w2l, OUTCH * KDIM / 4);
    {
        int n4 = (int)((size_t)BATCH * KDIM * HW / 4);
        convert_split<<<(n4 + 255) / 256, 256>>>(features, fh, fl, n4);
    }

    gemm_pipe<KDIM, true><<<dim3(25, 2, BATCH), 256, GEMM_SMEM>>>(w1h, w1l, fh, fl, b1);
    gemm_pipe<OUTCH, false><<<dim3(25, 1, BATCH), 256, GEMM_SMEM>>>(w2h, w2l, hh, hl, b2);

    head_kernel<<<dim3(25, A_NUM, BATCH), 256>>>(anc, bboxes, iou_out);
    loss_part<<<32, 64>>>(pos_idx, neg_idx, gt_off);
    loss_final<<<1, 1>>>(loss_out);
    class_kernel<<<(MPOS * C_NUM + 255) / 256, 256>>>(pos_idx, cls_out);
}